// round 5
// baseline (speedup 1.0000x reference)
#include <cuda_runtime.h>
#include <cuda_bf16.h>
#include <mma.h>
#include <cstdint>

using namespace nvcuda;

#define NN 50000
#define NE 800000
#define DIM 128
#define NCLS 10
#define NG 64
#define NT ((NN + 127) / 128)   // 391 M-tiles

// ---------------- static device scratch ----------------
__device__ __align__(16) float g_Aagg[NT * 128 * DIM]; // normalized agg (GEMM A), fp32
__device__ float g_pool[NG * DIM];                     // pooled sums (atomic accum)
__device__ float g_outnorm[NN];
__device__ int   g_outdeg_i[NN];
__device__ int   g_indeg_i[NN];
__device__ int   g_rowptr[NN + 1];
__device__ int   g_cursor[NN];
__device__ int   g_esrc[NE];
__device__ int   g_start[NG + 1];
__device__ int   g_is64;

// ---------------- helpers ----------------
__device__ __forceinline__ int idx_at(const void* buf, int i, int is64) {
    return is64 ? (int)((const long long*)buf)[i] : ((const int*)buf)[i];
}

// each block derives the index width locally: if buffer is int64, all odd
// 32-bit words are zero (values < 50000). 32 samples -> FP prob ~1e-150.
__device__ __forceinline__ int detect_is64_block(const void* src, int* sflag) {
    if (threadIdx.x < 32) {
        const int* p = (const int*)src;
        int z = (p[2 * threadIdx.x + 1] == 0);
        unsigned m = __ballot_sync(0xffffffffu, z);
        if (threadIdx.x == 0) *sflag = (m == 0xffffffffu);
    }
    __syncthreads();
    return *sflag;
}

// ------------- fused init: detect + zero + bounds + degree ----------------
// grid covers NE (3125 blocks x 256)
__global__ void init_kernel(const void* src, const void* dst, const void* gids) {
    __shared__ int sflag;
    int is64 = detect_is64_block(src, &sflag);
    int i = blockIdx.x * blockDim.x + threadIdx.x;

    if (i == 0) g_is64 = is64;

    if (i < NN) { g_outdeg_i[i] = 0; g_indeg_i[i] = 0; }
    if (i < NG * DIM) g_pool[i] = 0.f;
    {   // zero A tail rows (pad to full last tile)
        const int TAIL = NT * 128 * DIM - NN * DIM;  // 6144
        if (i < TAIL) g_Aagg[NN * DIM + i] = 0.f;
    }

    if (i < NN) {   // graph boundaries (graph_ids sorted ascending)
        int g = idx_at(gids, i, is64);
        int gp = (i > 0) ? idx_at(gids, i - 1, is64) : -1;
        for (int gg = gp + 1; gg <= g; gg++) g_start[gg] = i;
        if (i == NN - 1)
            for (int gg = g + 1; gg <= NG; gg++) g_start[gg] = NN;
    }
}

// degrees need the zeroed counters -> separate kernel after init
__global__ void degree_kernel(const void* src, const void* dst) {
    __shared__ int sflag;
    int is64 = detect_is64_block(src, &sflag);
    int e = blockIdx.x * blockDim.x + threadIdx.x;
    if (e >= NE) return;
    atomicAdd(&g_outdeg_i[idx_at(src, e, is64)], 1);
    atomicAdd(&g_indeg_i[idx_at(dst, e, is64)], 1);
}

// ------------- prefix sum of in-degrees -> rowptr/cursor; + out-norms -------
__global__ void scan_kernel() {
    __shared__ int sums[1024];
    int t = threadIdx.x;
    const int CH = (NN + 1023) / 1024;
    int beg = t * CH, end = min(beg + CH, NN);
    int s = 0;
    for (int i = beg; i < end; i++) s += g_indeg_i[i];
    sums[t] = s;
    __syncthreads();
    for (int off = 1; off < 1024; off <<= 1) {
        int v = (t >= off) ? sums[t - off] : 0;
        __syncthreads();
        sums[t] += v;
        __syncthreads();
    }
    int run = (t > 0) ? sums[t - 1] : 0;
    for (int i = beg; i < end; i++) {
        g_rowptr[i] = run; g_cursor[i] = run;
        run += g_indeg_i[i];
    }
    if (t == 0) g_rowptr[NN] = NE;
    // fused out-degree norms
    for (int i = beg; i < end; i++)
        g_outnorm[i] = rsqrtf(fmaxf((float)g_outdeg_i[i], 1.f));
}

// ---------------- fill dst-sorted edge list ----------------
__global__ void fill_kernel(const void* src, const void* dst) {
    __shared__ int sflag;
    int is64 = detect_is64_block(src, &sflag);
    int e = blockIdx.x * blockDim.x + threadIdx.x;
    if (e >= NE) return;
    int s = idx_at(src, e, is64);
    int d = idx_at(dst, e, is64);
    int pos = atomicAdd(&g_cursor[d], 1);
    g_esrc[pos] = s;
}

// ---------------- gather: one warp per dst node, 2-edge unroll ----------------
// A[d] = in_norm(d) * sum_{e in CSR(d)} out_norm(src) * feat[src]
__global__ void gather_kernel(const float* __restrict__ feat) {
    int w = (blockIdx.x * blockDim.x + threadIdx.x) >> 5;
    if (w >= NN) return;
    int lane = threadIdx.x & 31;
    int beg = g_rowptr[w], end = g_rowptr[w + 1];

    const float4* f4 = (const float4*)feat;
    float4 a0 = make_float4(0.f, 0.f, 0.f, 0.f);
    float4 a1 = make_float4(0.f, 0.f, 0.f, 0.f);

    int e = beg;
    for (; e + 2 <= end; e += 2) {
        int s0 = g_esrc[e], s1 = g_esrc[e + 1];
        float on0 = g_outnorm[s0], on1 = g_outnorm[s1];
        float4 v0 = f4[s0 * 32 + lane];
        float4 v1 = f4[s1 * 32 + lane];
        a0.x += v0.x * on0; a0.y += v0.y * on0; a0.z += v0.z * on0; a0.w += v0.w * on0;
        a1.x += v1.x * on1; a1.y += v1.y * on1; a1.z += v1.z * on1; a1.w += v1.w * on1;
    }
    if (e < end) {
        int s0 = g_esrc[e];
        float on0 = g_outnorm[s0];
        float4 v0 = f4[s0 * 32 + lane];
        a0.x += v0.x * on0; a0.y += v0.y * on0; a0.z += v0.z * on0; a0.w += v0.w * on0;
    }
    float inn = rsqrtf(fmaxf((float)(end - beg), 1.f));
    float4 acc;
    acc.x = (a0.x + a1.x) * inn; acc.y = (a0.y + a1.y) * inn;
    acc.z = (a0.z + a1.z) * inn; acc.w = (a0.w + a1.w) * inn;
    ((float4*)g_Aagg)[w * 32 + lane] = acc;
}

// -------- WMMA tf32 GEMM + fused bias/relu/segment-pool epilogue ------------
// 128x128 tile, full K=128 in smem. 8 warps, warp-tile 32x64 (2x4 frags).
#define SPAD 132
#define SM_BIAS 0
#define SM_GID  512
#define SM_AB   1024
#define SMEM_GEMM (SM_AB + 2 * 128 * SPAD * 4)   // 136192 B

__global__ __launch_bounds__(256)
void gemm_pool_kernel(const float* __restrict__ W, const float* __restrict__ bias,
                      const void* gids) {
    extern __shared__ unsigned char smraw[];
    float* sBias = (float*)(smraw + SM_BIAS);       // 128 floats
    int*   sGid  = (int*)(smraw + SM_GID);          // 128 ints
    float* As = (float*)(smraw + SM_AB);            // 128 x 132
    float* Bs = As + 128 * SPAD;                    // 128 x 132 (W row-major)
    float* Cs = As;                                 // epilogue reuse

    int tid = threadIdx.x;
    int wid = tid >> 5;
    int m0 = blockIdx.x * 128;
    int is64 = g_is64;

    if (tid < 128) {
        sBias[tid] = bias[tid];
        int grow = m0 + tid;
        sGid[tid] = (grow < NN) ? idx_at(gids, grow, is64) : -1;
    }

    // load A tile + W into padded smem
    {
        const float4* pa = (const float4*)(g_Aagg + (size_t)m0 * DIM);
        const float4* pw = (const float4*)W;
        float4* sa = (float4*)As;
        float4* sb = (float4*)Bs;
        #pragma unroll
        for (int i = 0; i < 16; i++) {
            int idx = tid + i * 256;
            int r = idx >> 5, c = idx & 31;
            sa[r * 33 + c] = pa[idx];
            sb[r * 33 + c] = pw[idx];
        }
    }
    __syncthreads();

    int wm = (wid >> 1) * 32;
    int wn = (wid & 1) * 64;

    wmma::fragment<wmma::accumulator, 16, 16, 8, float> acc[2][4];
    #pragma unroll
    for (int i = 0; i < 2; i++)
        #pragma unroll
        for (int j = 0; j < 4; j++)
            wmma::fill_fragment(acc[i][j], 0.f);

    #pragma unroll
    for (int k0 = 0; k0 < DIM; k0 += 8) {
        wmma::fragment<wmma::matrix_a, 16, 16, 8, wmma::precision::tf32, wmma::row_major> a[2];
        wmma::fragment<wmma::matrix_b, 16, 16, 8, wmma::precision::tf32, wmma::row_major> b[4];
        #pragma unroll
        for (int i = 0; i < 2; i++) {
            wmma::load_matrix_sync(a[i], &As[(wm + i * 16) * SPAD + k0], SPAD);
            #pragma unroll
            for (int t = 0; t < a[i].num_elements; t++)
                a[i].x[t] = wmma::__float_to_tf32(a[i].x[t]);
        }
        #pragma unroll
        for (int j = 0; j < 4; j++) {
            wmma::load_matrix_sync(b[j], &Bs[k0 * SPAD + wn + j * 16], SPAD);
            #pragma unroll
            for (int t = 0; t < b[j].num_elements; t++)
                b[j].x[t] = wmma::__float_to_tf32(b[j].x[t]);
        }
        #pragma unroll
        for (int i = 0; i < 2; i++)
            #pragma unroll
            for (int j = 0; j < 4; j++)
                wmma::mma_sync(acc[i][j], a[i], b[j], acc[i][j]);
    }
    __syncthreads();   // done reading As/Bs; Cs aliases As

    #pragma unroll
    for (int i = 0; i < 2; i++)
        #pragma unroll
        for (int j = 0; j < 4; j++)
            wmma::store_matrix_sync(&Cs[(wm + i * 16) * SPAD + wn + j * 16],
                                    acc[i][j], SPAD, wmma::mem_row_major);
    __syncthreads();

    // fused bias + relu + segmented row-sum by graph id -> atomic pool accum
    {
        int c = tid & 127;
        int half = tid >> 7;          // 0..1 -> rows [half*64, half*64+64)
        int r = half * 64;
        int rend = r + 64;
        float bv = sBias[c];
        if (m0 + r < NN) {
            int cur = sGid[r];
            float run = 0.f;
            for (; r < rend; r++) {
                if (m0 + r >= NN) break;
                int g = sGid[r];
                if (g != cur) {
                    atomicAdd(&g_pool[cur * DIM + c], run);
                    run = 0.f; cur = g;
                }
                run += fmaxf(Cs[r * SPAD + c] + bv, 0.f);
            }
            atomicAdd(&g_pool[cur * DIM + c], run);
        }
    }
}

// ---------------- head: out = (pool/cnt) @ Wh + bh ----------------
__global__ void head_kernel(const float* __restrict__ Wh,
                            const float* __restrict__ bh,
                            float* __restrict__ out) {
    __shared__ float pooled[DIM];
    int g = blockIdx.x;
    int c = threadIdx.x;
    float cnt = fmaxf((float)(g_start[g + 1] - g_start[g]), 1.f);
    pooled[c] = g_pool[g * DIM + c] / cnt;
    __syncthreads();
    if (c < NCLS) {
        float acc = bh[c];
        #pragma unroll 4
        for (int d = 0; d < DIM; d++) acc += pooled[d] * Wh[d * NCLS + c];
        out[g * NCLS + c] = acc;
    }
}

// ---------------- launch ----------------
extern "C" void kernel_launch(void* const* d_in, const int* in_sizes, int n_in,
                              void* d_out, int out_size) {
    const float* feat = (const float*)d_in[0];
    const void*  src  = d_in[1];
    const void*  dst  = d_in[2];
    const void*  gids = d_in[3];
    const float* W    = (const float*)d_in[4];
    const float* b    = (const float*)d_in[5];
    const float* Wh   = (const float*)d_in[6];
    const float* bh   = (const float*)d_in[7];
    float* out = (float*)d_out;

    cudaFuncSetAttribute(gemm_pool_kernel,
                         cudaFuncAttributeMaxDynamicSharedMemorySize, SMEM_GEMM);

    init_kernel<<<(NE + 255) / 256, 256>>>(src, dst, gids);
    degree_kernel<<<(NE + 255) / 256, 256>>>(src, dst);
    scan_kernel<<<1, 1024>>>();
    fill_kernel<<<(NE + 255) / 256, 256>>>(src, dst);
    gather_kernel<<<(NN * 32 + 255) / 256, 256>>>(feat);
    gemm_pool_kernel<<<NT, 256, SMEM_GEMM>>>(W, b, gids);
    head_kernel<<<NG, DIM>>>(Wh, bh, out);
}

// round 6
// speedup vs baseline: 1.0797x; 1.0797x over previous
#include <cuda_runtime.h>
#include <cuda_fp16.h>
#include <mma.h>
#include <cstdint>

using namespace nvcuda;

#define NN 50000
#define NE 800000
#define DIM 128
#define NCLS 10
#define NG 64
#define NT ((NN + 127) / 128)   // 391 M-tiles

// ---------------- static device scratch ----------------
__device__ __align__(16) float g_Aagg[NT * 128 * DIM]; // normalized agg (GEMM A), fp32
__device__ __align__(16) float g_h2[NN * DIM];         // relu(A@W + b)
__device__ __align__(16) uint2 g_feat16[NN * 32];      // fp16 features pre-scaled by out_norm
__device__ int   g_outdeg_i[NN];
__device__ int   g_indeg_i[NN];
__device__ int   g_rowptr[NN + 1];
__device__ int   g_cursor[NN];
__device__ int   g_esrc[NE];
__device__ int   g_start[NG + 1];
__device__ int   g_is64;

// ---------------- helpers ----------------
__device__ __forceinline__ int idx_at(const void* buf, int i, int is64) {
    return is64 ? (int)((const long long*)buf)[i] : ((const int*)buf)[i];
}

// ---------------- index dtype detection (1 warp) ----------------
__global__ void detect_kernel(const void* src) {
    const int* p = (const int*)src;
    int t = threadIdx.x;
    int z = (p[2 * t + 1] == 0);
    unsigned m = __ballot_sync(0xffffffffu, z);
    if (t == 0) g_is64 = (m == 0xffffffffu);
}

// ---------------- zero degree counters + A tail rows ----------------
__global__ void zero_kernel() {
    int i = blockIdx.x * blockDim.x + threadIdx.x;
    if (i < NN) { g_outdeg_i[i] = 0; g_indeg_i[i] = 0; }
    const int TAIL = NT * 128 * DIM - NN * DIM;  // 6144
    if (i < TAIL) g_Aagg[NN * DIM + i] = 0.f;
}

// ---------------- degrees (int atomics) ----------------
__global__ void degree_kernel(const void* src, const void* dst) {
    int e = blockIdx.x * blockDim.x + threadIdx.x;
    if (e >= NE) return;
    int is64 = g_is64;
    atomicAdd(&g_outdeg_i[idx_at(src, e, is64)], 1);
    atomicAdd(&g_indeg_i[idx_at(dst, e, is64)], 1);
}

// ------- prescale: feat16[n] = fp16(feat[n] * rsqrt(max(outdeg[n],1))) ------
__global__ void prescale_kernel(const float* __restrict__ feat) {
    int i = blockIdx.x * blockDim.x + threadIdx.x;   // one uint2 (4 halves) each
    if (i >= NN * 32) return;
    int n = i >> 5;
    float on = rsqrtf(fmaxf((float)g_outdeg_i[n], 1.f));
    float4 v = ((const float4*)feat)[i];
    __half2 h0 = __floats2half2_rn(v.x * on, v.y * on);
    __half2 h1 = __floats2half2_rn(v.z * on, v.w * on);
    uint2 u;
    u.x = *reinterpret_cast<unsigned*>(&h0);
    u.y = *reinterpret_cast<unsigned*>(&h1);
    g_feat16[i] = u;
}

// ---------------- prefix sum of in-degrees -> rowptr & cursor ----------------
__global__ void scan_kernel() {
    __shared__ int sums[1024];
    int t = threadIdx.x;
    const int CH = (NN + 1023) / 1024;
    int beg = t * CH, end = min(beg + CH, NN);
    int s = 0;
    for (int i = beg; i < end; i++) s += g_indeg_i[i];
    sums[t] = s;
    __syncthreads();
    for (int off = 1; off < 1024; off <<= 1) {
        int v = (t >= off) ? sums[t - off] : 0;
        __syncthreads();
        sums[t] += v;
        __syncthreads();
    }
    int run = (t > 0) ? sums[t - 1] : 0;
    for (int i = beg; i < end; i++) {
        g_rowptr[i] = run; g_cursor[i] = run;
        run += g_indeg_i[i];
    }
    if (t == 0) g_rowptr[NN] = NE;
}

// ---------------- fill dst-sorted edge list ----------------
__global__ void fill_kernel(const void* src, const void* dst) {
    int e = blockIdx.x * blockDim.x + threadIdx.x;
    if (e >= NE) return;
    int is64 = g_is64;
    int s = idx_at(src, e, is64);
    int d = idx_at(dst, e, is64);
    int pos = atomicAdd(&g_cursor[d], 1);
    g_esrc[pos] = s;
}

// ---------- gather (fp16 feats): one warp per dst node, 2-edge unroll --------
// A[d] = in_norm(d) * sum_{e in CSR(d)} feat16[src]   (out_norm pre-applied)
__global__ void gather_kernel() {
    int w = (blockIdx.x * blockDim.x + threadIdx.x) >> 5;
    if (w >= NN) return;
    int lane = threadIdx.x & 31;
    int beg = g_rowptr[w], end = g_rowptr[w + 1];

    float4 a0 = make_float4(0.f, 0.f, 0.f, 0.f);
    float4 a1 = make_float4(0.f, 0.f, 0.f, 0.f);

    int e = beg;
    for (; e + 2 <= end; e += 2) {
        int s0 = g_esrc[e], s1 = g_esrc[e + 1];
        uint2 u0 = g_feat16[s0 * 32 + lane];
        uint2 u1 = g_feat16[s1 * 32 + lane];
        float2 f00 = __half22float2(*reinterpret_cast<__half2*>(&u0.x));
        float2 f01 = __half22float2(*reinterpret_cast<__half2*>(&u0.y));
        float2 f10 = __half22float2(*reinterpret_cast<__half2*>(&u1.x));
        float2 f11 = __half22float2(*reinterpret_cast<__half2*>(&u1.y));
        a0.x += f00.x; a0.y += f00.y; a0.z += f01.x; a0.w += f01.y;
        a1.x += f10.x; a1.y += f10.y; a1.z += f11.x; a1.w += f11.y;
    }
    if (e < end) {
        int s0 = g_esrc[e];
        uint2 u0 = g_feat16[s0 * 32 + lane];
        float2 f00 = __half22float2(*reinterpret_cast<__half2*>(&u0.x));
        float2 f01 = __half22float2(*reinterpret_cast<__half2*>(&u0.y));
        a0.x += f00.x; a0.y += f00.y; a0.z += f01.x; a0.w += f01.y;
    }
    float inn = rsqrtf(fmaxf((float)(end - beg), 1.f));
    float4 acc;
    acc.x = (a0.x + a1.x) * inn; acc.y = (a0.y + a1.y) * inn;
    acc.z = (a0.z + a1.z) * inn; acc.w = (a0.w + a1.w) * inn;
    ((float4*)g_Aagg)[w * 32 + lane] = acc;
}

// ---------------- WMMA tf32 GEMM: h2 = relu(A @ W + b) ----------------
// 128x128 tile, full K=128 in smem. 8 warps, warp-tile 32x64 (2x4 wmma frags).
#define SPAD 132                       // fp32 row stride in smem
#define SMEM_GEMM (512 + 2 * 128 * SPAD * 4)   // bias + As + Bs = 135680 B

__global__ __launch_bounds__(256)
void gemm_tc_kernel(const float* __restrict__ W, const float* __restrict__ bias) {
    extern __shared__ unsigned char smraw[];
    float* sBias = (float*)smraw;                  // 128 floats
    float* As = (float*)(smraw + 512);             // 128 x 132
    float* Bs = As + 128 * SPAD;                   // 128 x 132  (W row-major)
    float* Cs = As;                                // epilogue reuse

    int tid = threadIdx.x;
    int wid = tid >> 5;
    int m0 = blockIdx.x * 128;

    if (tid < 128) sBias[tid] = bias[tid];

    // load A tile + W into padded smem (float4 granularity: 33 per row)
    {
        const float4* pa = (const float4*)(g_Aagg + (size_t)m0 * DIM);
        const float4* pw = (const float4*)W;
        float4* sa = (float4*)As;
        float4* sb = (float4*)Bs;
        #pragma unroll
        for (int i = 0; i < 16; i++) {
            int idx = tid + i * 256;      // 0..4095
            int r = idx >> 5, c = idx & 31;
            sa[r * 33 + c] = pa[idx];
            sb[r * 33 + c] = pw[idx];
        }
    }
    __syncthreads();

    int wm = (wid >> 1) * 32;   // 0,32,64,96
    int wn = (wid & 1) * 64;    // 0,64

    wmma::fragment<wmma::accumulator, 16, 16, 8, float> acc[2][4];
    #pragma unroll
    for (int i = 0; i < 2; i++)
        #pragma unroll
        for (int j = 0; j < 4; j++)
            wmma::fill_fragment(acc[i][j], 0.f);

    #pragma unroll
    for (int k0 = 0; k0 < DIM; k0 += 8) {
        wmma::fragment<wmma::matrix_a, 16, 16, 8, wmma::precision::tf32, wmma::row_major> a[2];
        wmma::fragment<wmma::matrix_b, 16, 16, 8, wmma::precision::tf32, wmma::row_major> b[4];
        #pragma unroll
        for (int i = 0; i < 2; i++) {
            wmma::load_matrix_sync(a[i], &As[(wm + i * 16) * SPAD + k0], SPAD);
            #pragma unroll
            for (int t = 0; t < a[i].num_elements; t++)
                a[i].x[t] = wmma::__float_to_tf32(a[i].x[t]);
        }
        #pragma unroll
        for (int j = 0; j < 4; j++) {
            wmma::load_matrix_sync(b[j], &Bs[k0 * SPAD + wn + j * 16], SPAD);
            #pragma unroll
            for (int t = 0; t < b[j].num_elements; t++)
                b[j].x[t] = wmma::__float_to_tf32(b[j].x[t]);
        }
        #pragma unroll
        for (int i = 0; i < 2; i++)
            #pragma unroll
            for (int j = 0; j < 4; j++)
                wmma::mma_sync(acc[i][j], a[i], b[j], acc[i][j]);
    }
    __syncthreads();   // done reading As/Bs; Cs aliases As

    #pragma unroll
    for (int i = 0; i < 2; i++)
        #pragma unroll
        for (int j = 0; j < 4; j++)
            wmma::store_matrix_sync(&Cs[(wm + i * 16) * SPAD + wn + j * 16],
                                    acc[i][j], SPAD, wmma::mem_row_major);
    __syncthreads();

    // bias + relu + write out
    const float4* c4 = (const float4*)Cs;
    float4* h4 = (float4*)g_h2;
    #pragma unroll
    for (int i = 0; i < 16; i++) {
        int idx = tid + i * 256;
        int r = idx >> 5, c = idx & 31;
        int grow = m0 + r;
        if (grow < NN) {
            float4 v = c4[r * 33 + c];
            float4 o;
            o.x = fmaxf(v.x + sBias[c * 4 + 0], 0.f);
            o.y = fmaxf(v.y + sBias[c * 4 + 1], 0.f);
            o.z = fmaxf(v.z + sBias[c * 4 + 2], 0.f);
            o.w = fmaxf(v.w + sBias[c * 4 + 3], 0.f);
            h4[(size_t)grow * 32 + c] = o;
        }
    }
}

// ---------------- graph boundaries (graph_ids sorted ascending) -------------
__global__ void bounds_kernel(const void* gids) {
    int i = blockIdx.x * blockDim.x + threadIdx.x;
    if (i >= NN) return;
    int is64 = g_is64;
    int g = idx_at(gids, i, is64);
    int gp = (i > 0) ? idx_at(gids, i - 1, is64) : -1;
    for (int gg = gp + 1; gg <= g; gg++) g_start[gg] = i;
    if (i == NN - 1)
        for (int gg = g + 1; gg <= NG; gg++) g_start[gg] = NN;
}

// ---------------- segment-mean pool + head GEMM -----------------------------
// 512 threads: 4 row-groups x 128 cols (MLP=4), then reduce.
__global__ void pool_head_kernel(const float* __restrict__ Wh,
                                 const float* __restrict__ bh,
                                 float* __restrict__ out) {
    __shared__ float part[4][DIM];
    __shared__ float pooled[DIM];
    int g = blockIdx.x;
    int c = threadIdx.x & 127;
    int rg = threadIdx.x >> 7;   // 0..3
    int s = g_start[g], e = g_start[g + 1];
    float sum = 0.f;
    for (int r = s + rg; r < e; r += 4) sum += g_h2[(size_t)r * DIM + c];
    part[rg][c] = sum;
    __syncthreads();
    if (rg == 0) {
        float cnt = fmaxf((float)(e - s), 1.f);
        pooled[c] = (part[0][c] + part[1][c] + part[2][c] + part[3][c]) / cnt;
    }
    __syncthreads();
    if (rg == 0 && c < NCLS) {
        float acc = bh[c];
        #pragma unroll 4
        for (int d = 0; d < DIM; d++) acc += pooled[d] * Wh[d * NCLS + c];
        out[g * NCLS + c] = acc;
    }
}

// ---------------- launch ----------------
extern "C" void kernel_launch(void* const* d_in, const int* in_sizes, int n_in,
                              void* d_out, int out_size) {
    const float* feat = (const float*)d_in[0];
    const void*  src  = d_in[1];
    const void*  dst  = d_in[2];
    const void*  gids = d_in[3];
    const float* W    = (const float*)d_in[4];
    const float* b    = (const float*)d_in[5];
    const float* Wh   = (const float*)d_in[6];
    const float* bh   = (const float*)d_in[7];
    float* out = (float*)d_out;

    cudaFuncSetAttribute(gemm_tc_kernel,
                         cudaFuncAttributeMaxDynamicSharedMemorySize, SMEM_GEMM);

    detect_kernel<<<1, 32>>>(src);
    zero_kernel<<<(NN + 255) / 256, 256>>>();
    degree_kernel<<<(NE + 255) / 256, 256>>>(src, dst);
    prescale_kernel<<<(NN * 32 + 255) / 256, 256>>>(feat);
    scan_kernel<<<1, 1024>>>();
    fill_kernel<<<(NE + 255) / 256, 256>>>(src, dst);
    gather_kernel<<<(NN * 32 + 255) / 256, 256>>>();
    bounds_kernel<<<(NN + 255) / 256, 256>>>(gids);
    gemm_tc_kernel<<<NT, 256, SMEM_GEMM>>>(W, b);
    pool_head_kernel<<<NG, 512>>>(Wh, bh, out);
}

// round 7
// speedup vs baseline: 1.5217x; 1.4095x over previous
#include <cuda_runtime.h>
#include <mma.h>
#include <cstdint>

using namespace nvcuda;

#define NN 50000
#define NE 800000
#define DIM 128
#define NCLS 10
#define NG 64
#define NT ((NN + 127) / 128)   // 391 M-tiles

// ---------------- static device scratch ----------------
__device__ __align__(16) float g_Aagg[NT * 128 * DIM]; // normalized agg (GEMM A), fp32
__device__ __align__(16) float g_h2[NN * DIM];         // relu(A@W + b)
__device__ float g_outnorm[NN];
__device__ int   g_outdeg_i[NN];
__device__ int   g_indeg_i[NN];
__device__ int   g_rowptr[NN + 1];
__device__ int   g_cursor[NN];
__device__ int   g_esrc[NE];
__device__ int   g_start[NG + 1];
__device__ int   g_is64;

// ---------------- helpers ----------------
__device__ __forceinline__ int idx_at(const void* buf, int i, int is64) {
    return is64 ? (int)((const long long*)buf)[i] : ((const int*)buf)[i];
}

// ---------------- index dtype detection (1 warp) ----------------
__global__ void detect_kernel(const void* src) {
    const int* p = (const int*)src;
    int t = threadIdx.x;
    int z = (p[2 * t + 1] == 0);
    unsigned m = __ballot_sync(0xffffffffu, z);
    if (t == 0) g_is64 = (m == 0xffffffffu);
}

// ---------------- zero degree counters + A tail rows ----------------
__global__ void zero_kernel() {
    int i = blockIdx.x * blockDim.x + threadIdx.x;
    if (i < NN) { g_outdeg_i[i] = 0; g_indeg_i[i] = 0; }
    const int TAIL = NT * 128 * DIM - NN * DIM;  // 6144
    if (i < TAIL) g_Aagg[NN * DIM + i] = 0.f;
}

// ---------------- degrees (int atomics) ----------------
__global__ void degree_kernel(const void* src, const void* dst) {
    int e = blockIdx.x * blockDim.x + threadIdx.x;
    if (e >= NE) return;
    int is64 = g_is64;
    atomicAdd(&g_outdeg_i[idx_at(src, e, is64)], 1);
    atomicAdd(&g_indeg_i[idx_at(dst, e, is64)], 1);
}

// ------- smem-staged prefix sum -> rowptr & cursor; + fused out-norms -------
// 1 block, 1024 threads, 204 KB dynamic smem. All gmem traffic coalesced.
#define SCAN_CH ((NN + 1023) / 1024)     // 49
#define SMEM_SCAN ((NN + 1024) * 4)      // 204096 B

__global__ void scan_kernel() {
    extern __shared__ int sdeg[];        // [NN] degrees -> prefixes
    int* sums = sdeg + NN;               // [1024] per-thread chunk sums
    int t = threadIdx.x;

    // coalesced load of in-degrees into smem
    for (int i = t; i < NN; i += 1024) sdeg[i] = g_indeg_i[i];
    __syncthreads();

    int beg = t * SCAN_CH, end = min(beg + SCAN_CH, NN);
    int s = 0;
    for (int i = beg; i < end; i++) s += sdeg[i];   // stride-49: bank-conflict-free
    sums[t] = s;
    __syncthreads();
    for (int off = 1; off < 1024; off <<= 1) {
        int v = (t >= off) ? sums[t - off] : 0;
        __syncthreads();
        sums[t] += v;
        __syncthreads();
    }
    int run = (t > 0) ? sums[t - 1] : 0;
    for (int i = beg; i < end; i++) {   // in-place: read deg, write prefix
        int d = sdeg[i];
        sdeg[i] = run;
        run += d;
    }
    __syncthreads();

    // coalesced store rowptr + cursor, fused out-degree norms
    for (int i = t; i < NN; i += 1024) {
        int v = sdeg[i];
        g_rowptr[i] = v;
        g_cursor[i] = v;
        g_outnorm[i] = rsqrtf(fmaxf((float)g_outdeg_i[i], 1.f));
    }
    if (t == 0) g_rowptr[NN] = NE;
}

// ---------------- fill dst-sorted edge list ----------------
__global__ void fill_kernel(const void* src, const void* dst) {
    int e = blockIdx.x * blockDim.x + threadIdx.x;
    if (e >= NE) return;
    int is64 = g_is64;
    int s = idx_at(src, e, is64);
    int d = idx_at(dst, e, is64);
    int pos = atomicAdd(&g_cursor[d], 1);
    g_esrc[pos] = s;
}

// ------- gather: one warp per dst node, shfl-broadcast indices, MLP=4 -------
// A[d] = in_norm(d) * sum_{e in CSR(d)} out_norm(src) * feat[src]
__global__ void gather_kernel(const float* __restrict__ feat) {
    int w = (blockIdx.x * blockDim.x + threadIdx.x) >> 5;
    if (w >= NN) return;
    int lane = threadIdx.x & 31;
    int beg = g_rowptr[w], end = g_rowptr[w + 1];

    const float4* f4 = (const float4*)feat;
    float4 a0 = make_float4(0.f, 0.f, 0.f, 0.f);
    float4 a1 = make_float4(0.f, 0.f, 0.f, 0.f);

    for (int base = beg; base < end; base += 32) {
        int n = min(32, end - base);
        // one coalesced index load per 32-edge window
        int sl = (base + lane < end) ? g_esrc[base + lane] : 0;
        int j = 0;
        for (; j + 4 <= n; j += 4) {
            int s0 = __shfl_sync(0xffffffffu, sl, j);
            int s1 = __shfl_sync(0xffffffffu, sl, j + 1);
            int s2 = __shfl_sync(0xffffffffu, sl, j + 2);
            int s3 = __shfl_sync(0xffffffffu, sl, j + 3);
            float on0 = g_outnorm[s0], on1 = g_outnorm[s1];
            float on2 = g_outnorm[s2], on3 = g_outnorm[s3];
            float4 v0 = f4[s0 * 32 + lane];
            float4 v1 = f4[s1 * 32 + lane];
            float4 v2 = f4[s2 * 32 + lane];
            float4 v3 = f4[s3 * 32 + lane];
            a0.x += v0.x * on0; a0.y += v0.y * on0; a0.z += v0.z * on0; a0.w += v0.w * on0;
            a1.x += v1.x * on1; a1.y += v1.y * on1; a1.z += v1.z * on1; a1.w += v1.w * on1;
            a0.x += v2.x * on2; a0.y += v2.y * on2; a0.z += v2.z * on2; a0.w += v2.w * on2;
            a1.x += v3.x * on3; a1.y += v3.y * on3; a1.z += v3.z * on3; a1.w += v3.w * on3;
        }
        for (; j < n; j++) {
            int s0 = __shfl_sync(0xffffffffu, sl, j);
            float on0 = g_outnorm[s0];
            float4 v0 = f4[s0 * 32 + lane];
            a0.x += v0.x * on0; a0.y += v0.y * on0; a0.z += v0.z * on0; a0.w += v0.w * on0;
        }
    }
    float inn = rsqrtf(fmaxf((float)(end - beg), 1.f));
    float4 acc;
    acc.x = (a0.x + a1.x) * inn; acc.y = (a0.y + a1.y) * inn;
    acc.z = (a0.z + a1.z) * inn; acc.w = (a0.w + a1.w) * inn;
    ((float4*)g_Aagg)[w * 32 + lane] = acc;
}

// ---------------- WMMA tf32 GEMM: h2 = relu(A @ W + b) ----------------
// 128x128 tile, full K=128 in smem. 8 warps, warp-tile 32x64 (2x4 wmma frags).
#define SPAD 132
#define SMEM_GEMM (512 + 2 * 128 * SPAD * 4)   // 135680 B

__global__ __launch_bounds__(256)
void gemm_tc_kernel(const float* __restrict__ W, const float* __restrict__ bias) {
    extern __shared__ unsigned char smraw[];
    float* sBias = (float*)smraw;                  // 128 floats
    float* As = (float*)(smraw + 512);             // 128 x 132
    float* Bs = As + 128 * SPAD;                   // 128 x 132  (W row-major)
    float* Cs = As;                                // epilogue reuse

    int tid = threadIdx.x;
    int wid = tid >> 5;
    int m0 = blockIdx.x * 128;

    if (tid < 128) sBias[tid] = bias[tid];

    {
        const float4* pa = (const float4*)(g_Aagg + (size_t)m0 * DIM);
        const float4* pw = (const float4*)W;
        float4* sa = (float4*)As;
        float4* sb = (float4*)Bs;
        #pragma unroll
        for (int i = 0; i < 16; i++) {
            int idx = tid + i * 256;
            int r = idx >> 5, c = idx & 31;
            sa[r * 33 + c] = pa[idx];
            sb[r * 33 + c] = pw[idx];
        }
    }
    __syncthreads();

    int wm = (wid >> 1) * 32;
    int wn = (wid & 1) * 64;

    wmma::fragment<wmma::accumulator, 16, 16, 8, float> acc[2][4];
    #pragma unroll
    for (int i = 0; i < 2; i++)
        #pragma unroll
        for (int j = 0; j < 4; j++)
            wmma::fill_fragment(acc[i][j], 0.f);

    #pragma unroll
    for (int k0 = 0; k0 < DIM; k0 += 8) {
        wmma::fragment<wmma::matrix_a, 16, 16, 8, wmma::precision::tf32, wmma::row_major> a[2];
        wmma::fragment<wmma::matrix_b, 16, 16, 8, wmma::precision::tf32, wmma::row_major> b[4];
        #pragma unroll
        for (int i = 0; i < 2; i++) {
            wmma::load_matrix_sync(a[i], &As[(wm + i * 16) * SPAD + k0], SPAD);
            #pragma unroll
            for (int t = 0; t < a[i].num_elements; t++)
                a[i].x[t] = wmma::__float_to_tf32(a[i].x[t]);
        }
        #pragma unroll
        for (int j = 0; j < 4; j++) {
            wmma::load_matrix_sync(b[j], &Bs[k0 * SPAD + wn + j * 16], SPAD);
            #pragma unroll
            for (int t = 0; t < b[j].num_elements; t++)
                b[j].x[t] = wmma::__float_to_tf32(b[j].x[t]);
        }
        #pragma unroll
        for (int i = 0; i < 2; i++)
            #pragma unroll
            for (int j = 0; j < 4; j++)
                wmma::mma_sync(acc[i][j], a[i], b[j], acc[i][j]);
    }
    __syncthreads();

    #pragma unroll
    for (int i = 0; i < 2; i++)
        #pragma unroll
        for (int j = 0; j < 4; j++)
            wmma::store_matrix_sync(&Cs[(wm + i * 16) * SPAD + wn + j * 16],
                                    acc[i][j], SPAD, wmma::mem_row_major);
    __syncthreads();

    const float4* c4 = (const float4*)Cs;
    float4* h4 = (float4*)g_h2;
    #pragma unroll
    for (int i = 0; i < 16; i++) {
        int idx = tid + i * 256;
        int r = idx >> 5, c = idx & 31;
        int grow = m0 + r;
        if (grow < NN) {
            float4 v = c4[r * 33 + c];
            float4 o;
            o.x = fmaxf(v.x + sBias[c * 4 + 0], 0.f);
            o.y = fmaxf(v.y + sBias[c * 4 + 1], 0.f);
            o.z = fmaxf(v.z + sBias[c * 4 + 2], 0.f);
            o.w = fmaxf(v.w + sBias[c * 4 + 3], 0.f);
            h4[(size_t)grow * 32 + c] = o;
        }
    }
}

// ---------------- graph boundaries (graph_ids sorted ascending) -------------
__global__ void bounds_kernel(const void* gids) {
    int i = blockIdx.x * blockDim.x + threadIdx.x;
    if (i >= NN) return;
    int is64 = g_is64;
    int g = idx_at(gids, i, is64);
    int gp = (i > 0) ? idx_at(gids, i - 1, is64) : -1;
    for (int gg = gp + 1; gg <= g; gg++) g_start[gg] = i;
    if (i == NN - 1)
        for (int gg = g + 1; gg <= NG; gg++) g_start[gg] = NN;
}

// ---------------- segment-mean pool + head GEMM -----------------------------
__global__ void pool_head_kernel(const float* __restrict__ Wh,
                                 const float* __restrict__ bh,
                                 float* __restrict__ out) {
    __shared__ float part[4][DIM];
    __shared__ float pooled[DIM];
    int g = blockIdx.x;
    int c = threadIdx.x & 127;
    int rg = threadIdx.x >> 7;   // 0..3
    int s = g_start[g], e = g_start[g + 1];
    float sum = 0.f;
    for (int r = s + rg; r < e; r += 4) sum += g_h2[(size_t)r * DIM + c];
    part[rg][c] = sum;
    __syncthreads();
    if (rg == 0) {
        float cnt = fmaxf((float)(e - s), 1.f);
        pooled[c] = (part[0][c] + part[1][c] + part[2][c] + part[3][c]) / cnt;
    }
    __syncthreads();
    if (rg == 0 && c < NCLS) {
        float acc = bh[c];
        #pragma unroll 4
        for (int d = 0; d < DIM; d++) acc += pooled[d] * Wh[d * NCLS + c];
        out[g * NCLS + c] = acc;
    }
}

// ---------------- launch ----------------
extern "C" void kernel_launch(void* const* d_in, const int* in_sizes, int n_in,
                              void* d_out, int out_size) {
    const float* feat = (const float*)d_in[0];
    const void*  src  = d_in[1];
    const void*  dst  = d_in[2];
    const void*  gids = d_in[3];
    const float* W    = (const float*)d_in[4];
    const float* b    = (const float*)d_in[5];
    const float* Wh   = (const float*)d_in[6];
    const float* bh   = (const float*)d_in[7];
    float* out = (float*)d_out;

    cudaFuncSetAttribute(gemm_tc_kernel,
                         cudaFuncAttributeMaxDynamicSharedMemorySize, SMEM_GEMM);
    cudaFuncSetAttribute(scan_kernel,
                         cudaFuncAttributeMaxDynamicSharedMemorySize, SMEM_SCAN);

    detect_kernel<<<1, 32>>>(src);
    zero_kernel<<<(NN + 255) / 256, 256>>>();
    degree_kernel<<<(NE + 255) / 256, 256>>>(src, dst);
    scan_kernel<<<1, 1024, SMEM_SCAN>>>();
    fill_kernel<<<(NE + 255) / 256, 256>>>(src, dst);
    gather_kernel<<<(NN * 32 + 255) / 256, 256>>>(feat);
    bounds_kernel<<<(NN + 255) / 256, 256>>>(gids);
    gemm_tc_kernel<<<NT, 256, SMEM_GEMM>>>(W, b);
    pool_head_kernel<<<NG, 512>>>(Wh, bh, out);
}

// round 8
// speedup vs baseline: 1.7795x; 1.1694x over previous
#include <cuda_runtime.h>
#include <mma.h>
#include <cstdint>

using namespace nvcuda;

#define NN 50000
#define NE 800000
#define DIM 128
#define NCLS 10
#define NG 64
#define NT ((NN + 127) / 128)       // 391 M-tiles
#define SB ((NN + 255) / 256)       // 196 scan blocks

// ---------------- static device scratch ----------------
__device__ __align__(16) float g_Aagg[NT * 128 * DIM]; // normalized agg (GEMM A), fp32
__device__ __align__(16) float g_h2[NN * DIM];         // relu(A@W + b)
__device__ float g_outnorm[NN];
__device__ int   g_outdeg_i[NN];
__device__ int   g_indeg_i[NN];
__device__ int   g_rowptr[NN + 1];
__device__ int   g_cursor[NN];
__device__ int   g_esrc[NE];
__device__ int   g_start[NG + 1];
__device__ int   g_bsum[SB];
__device__ int   g_bpre[SB];
__device__ int   g_is64;

// ---------------- helpers ----------------
__device__ __forceinline__ int idx_at(const void* buf, int i, int is64) {
    return is64 ? (int)((const long long*)buf)[i] : ((const int*)buf)[i];
}

// ---------------- index dtype detection (1 warp) ----------------
__global__ void detect_kernel(const void* src) {
    const int* p = (const int*)src;
    int t = threadIdx.x;
    int z = (p[2 * t + 1] == 0);
    unsigned m = __ballot_sync(0xffffffffu, z);
    if (t == 0) g_is64 = (m == 0xffffffffu);
}

// -------- zero degree counters + A tail rows + graph bounds (fused) --------
__global__ void zero_bounds_kernel(const void* gids) {
    int i = blockIdx.x * blockDim.x + threadIdx.x;
    if (i < NN) { g_outdeg_i[i] = 0; g_indeg_i[i] = 0; }
    const int TAIL = NT * 128 * DIM - NN * DIM;  // 6144
    if (i < TAIL) g_Aagg[NN * DIM + i] = 0.f;

    if (i < NN) {   // graph boundaries (graph_ids sorted ascending)
        int is64 = g_is64;
        int g = idx_at(gids, i, is64);
        int gp = (i > 0) ? idx_at(gids, i - 1, is64) : -1;
        for (int gg = gp + 1; gg <= g; gg++) g_start[gg] = i;
        if (i == NN - 1)
            for (int gg = g + 1; gg <= NG; gg++) g_start[gg] = NN;
    }
}

// ---------------- degrees (int atomics) ----------------
__global__ void degree_kernel(const void* src, const void* dst) {
    int e = blockIdx.x * blockDim.x + threadIdx.x;
    if (e >= NE) return;
    int is64 = g_is64;
    atomicAdd(&g_outdeg_i[idx_at(src, e, is64)], 1);
    atomicAdd(&g_indeg_i[idx_at(dst, e, is64)], 1);
}

// ---------------- hierarchical scan: partial -> spine -> apply ----------------
__global__ void scan_partial_kernel() {
    int i = blockIdx.x * 256 + threadIdx.x;
    int d = (i < NN) ? g_indeg_i[i] : 0;
    #pragma unroll
    for (int off = 16; off > 0; off >>= 1)
        d += __shfl_down_sync(0xffffffffu, d, off);
    __shared__ int ws[8];
    int wid = threadIdx.x >> 5, lane = threadIdx.x & 31;
    if (lane == 0) ws[wid] = d;
    __syncthreads();
    if (threadIdx.x < 8) {
        int v = ws[threadIdx.x];
        #pragma unroll
        for (int off = 4; off > 0; off >>= 1)
            v += __shfl_down_sync(0xffu, v, off);
        if (threadIdx.x == 0) g_bsum[blockIdx.x] = v;
    }
}

__global__ void scan_spine_kernel() {
    // 256 threads, SB=196 values: exclusive scan
    int t = threadIdx.x;
    int v = (t < SB) ? g_bsum[t] : 0;
    int lane = t & 31, wid = t >> 5;
    // inclusive scan within warp
    #pragma unroll
    for (int off = 1; off < 32; off <<= 1) {
        int n = __shfl_up_sync(0xffffffffu, v, off);
        if (lane >= off) v += n;
    }
    __shared__ int ws[8];
    if (lane == 31) ws[wid] = v;
    __syncthreads();
    if (t < 8) {
        int s = ws[t];
        #pragma unroll
        for (int off = 1; off < 8; off <<= 1) {
            int n = __shfl_up_sync(0xffu, s, off);
            if (t >= off) s += n;
        }
        ws[t] = s;
    }
    __syncthreads();
    int inc = v + (wid > 0 ? ws[wid - 1] : 0);
    int exc = inc - ((t < SB) ? g_bsum[t] : 0);
    if (t < SB) g_bpre[t] = exc;
}

__global__ void scan_apply_kernel() {
    int i = blockIdx.x * 256 + threadIdx.x;
    int d = (i < NN) ? g_indeg_i[i] : 0;
    int lane = threadIdx.x & 31, wid = threadIdx.x >> 5;
    int v = d;
    #pragma unroll
    for (int off = 1; off < 32; off <<= 1) {
        int n = __shfl_up_sync(0xffffffffu, v, off);
        if (lane >= off) v += n;
    }
    __shared__ int ws[8];
    if (lane == 31) ws[wid] = v;
    __syncthreads();
    if (threadIdx.x < 8) {
        int s = ws[threadIdx.x];
        #pragma unroll
        for (int off = 1; off < 8; off <<= 1) {
            int n = __shfl_up_sync(0xffu, s, off);
            if (threadIdx.x >= off) s += n;
        }
        ws[threadIdx.x] = s;
    }
    __syncthreads();
    int inc = v + (wid > 0 ? ws[wid - 1] : 0) + g_bpre[blockIdx.x];
    int exc = inc - d;
    if (i < NN) {
        g_rowptr[i] = exc;
        g_cursor[i] = exc;
        g_outnorm[i] = rsqrtf(fmaxf((float)g_outdeg_i[i], 1.f));
    }
    if (i == NN) g_rowptr[NN] = NE;
}

// ---------------- fill dst-sorted edge list ----------------
__global__ void fill_kernel(const void* src, const void* dst) {
    int e = blockIdx.x * blockDim.x + threadIdx.x;
    if (e >= NE) return;
    int is64 = g_is64;
    int s = idx_at(src, e, is64);
    int d = idx_at(dst, e, is64);
    int pos = atomicAdd(&g_cursor[d], 1);
    g_esrc[pos] = s;
}

// ------- gather: one warp per dst node, shfl-broadcast indices, MLP=4 -------
// A[d] = in_norm(d) * sum_{e in CSR(d)} out_norm(src) * feat[src]
__global__ void gather_kernel(const float* __restrict__ feat) {
    int w = (blockIdx.x * blockDim.x + threadIdx.x) >> 5;
    if (w >= NN) return;
    int lane = threadIdx.x & 31;
    int beg = g_rowptr[w], end = g_rowptr[w + 1];

    const float4* f4 = (const float4*)feat;
    float4 a0 = make_float4(0.f, 0.f, 0.f, 0.f);
    float4 a1 = make_float4(0.f, 0.f, 0.f, 0.f);

    for (int base = beg; base < end; base += 32) {
        int n = min(32, end - base);
        int sl = (base + lane < end) ? g_esrc[base + lane] : 0;
        int j = 0;
        for (; j + 4 <= n; j += 4) {
            int s0 = __shfl_sync(0xffffffffu, sl, j);
            int s1 = __shfl_sync(0xffffffffu, sl, j + 1);
            int s2 = __shfl_sync(0xffffffffu, sl, j + 2);
            int s3 = __shfl_sync(0xffffffffu, sl, j + 3);
            float on0 = g_outnorm[s0], on1 = g_outnorm[s1];
            float on2 = g_outnorm[s2], on3 = g_outnorm[s3];
            float4 v0 = f4[s0 * 32 + lane];
            float4 v1 = f4[s1 * 32 + lane];
            float4 v2 = f4[s2 * 32 + lane];
            float4 v3 = f4[s3 * 32 + lane];
            a0.x += v0.x * on0; a0.y += v0.y * on0; a0.z += v0.z * on0; a0.w += v0.w * on0;
            a1.x += v1.x * on1; a1.y += v1.y * on1; a1.z += v1.z * on1; a1.w += v1.w * on1;
            a0.x += v2.x * on2; a0.y += v2.y * on2; a0.z += v2.z * on2; a0.w += v2.w * on2;
            a1.x += v3.x * on3; a1.y += v3.y * on3; a1.z += v3.z * on3; a1.w += v3.w * on3;
        }
        for (; j < n; j++) {
            int s0 = __shfl_sync(0xffffffffu, sl, j);
            float on0 = g_outnorm[s0];
            float4 v0 = f4[s0 * 32 + lane];
            a0.x += v0.x * on0; a0.y += v0.y * on0; a0.z += v0.z * on0; a0.w += v0.w * on0;
        }
    }
    float inn = rsqrtf(fmaxf((float)(end - beg), 1.f));
    float4 acc;
    acc.x = (a0.x + a1.x) * inn; acc.y = (a0.y + a1.y) * inn;
    acc.z = (a0.z + a1.z) * inn; acc.w = (a0.w + a1.w) * inn;
    ((float4*)g_Aagg)[w * 32 + lane] = acc;
}

// ---------------- WMMA tf32 GEMM: h2 = relu(A @ W + b) ----------------
#define SPAD 132
#define SMEM_GEMM (512 + 2 * 128 * SPAD * 4)   // 135680 B

__global__ __launch_bounds__(256)
void gemm_tc_kernel(const float* __restrict__ W, const float* __restrict__ bias) {
    extern __shared__ unsigned char smraw[];
    float* sBias = (float*)smraw;                  // 128 floats
    float* As = (float*)(smraw + 512);             // 128 x 132
    float* Bs = As + 128 * SPAD;                   // 128 x 132  (W row-major)
    float* Cs = As;                                // epilogue reuse

    int tid = threadIdx.x;
    int wid = tid >> 5;
    int m0 = blockIdx.x * 128;

    if (tid < 128) sBias[tid] = bias[tid];

    {
        const float4* pa = (const float4*)(g_Aagg + (size_t)m0 * DIM);
        const float4* pw = (const float4*)W;
        float4* sa = (float4*)As;
        float4* sb = (float4*)Bs;
        #pragma unroll
        for (int i = 0; i < 16; i++) {
            int idx = tid + i * 256;
            int r = idx >> 5, c = idx & 31;
            sa[r * 33 + c] = pa[idx];
            sb[r * 33 + c] = pw[idx];
        }
    }
    __syncthreads();

    int wm = (wid >> 1) * 32;
    int wn = (wid & 1) * 64;

    wmma::fragment<wmma::accumulator, 16, 16, 8, float> acc[2][4];
    #pragma unroll
    for (int i = 0; i < 2; i++)
        #pragma unroll
        for (int j = 0; j < 4; j++)
            wmma::fill_fragment(acc[i][j], 0.f);

    #pragma unroll
    for (int k0 = 0; k0 < DIM; k0 += 8) {
        wmma::fragment<wmma::matrix_a, 16, 16, 8, wmma::precision::tf32, wmma::row_major> a[2];
        wmma::fragment<wmma::matrix_b, 16, 16, 8, wmma::precision::tf32, wmma::row_major> b[4];
        #pragma unroll
        for (int i = 0; i < 2; i++) {
            wmma::load_matrix_sync(a[i], &As[(wm + i * 16) * SPAD + k0], SPAD);
            #pragma unroll
            for (int t = 0; t < a[i].num_elements; t++)
                a[i].x[t] = wmma::__float_to_tf32(a[i].x[t]);
        }
        #pragma unroll
        for (int j = 0; j < 4; j++) {
            wmma::load_matrix_sync(b[j], &Bs[k0 * SPAD + wn + j * 16], SPAD);
            #pragma unroll
            for (int t = 0; t < b[j].num_elements; t++)
                b[j].x[t] = wmma::__float_to_tf32(b[j].x[t]);
        }
        #pragma unroll
        for (int i = 0; i < 2; i++)
            #pragma unroll
            for (int j = 0; j < 4; j++)
                wmma::mma_sync(acc[i][j], a[i], b[j], acc[i][j]);
    }
    __syncthreads();

    #pragma unroll
    for (int i = 0; i < 2; i++)
        #pragma unroll
        for (int j = 0; j < 4; j++)
            wmma::store_matrix_sync(&Cs[(wm + i * 16) * SPAD + wn + j * 16],
                                    acc[i][j], SPAD, wmma::mem_row_major);
    __syncthreads();

    const float4* c4 = (const float4*)Cs;
    float4* h4 = (float4*)g_h2;
    #pragma unroll
    for (int i = 0; i < 16; i++) {
        int idx = tid + i * 256;
        int r = idx >> 5, c = idx & 31;
        int grow = m0 + r;
        if (grow < NN) {
            float4 v = c4[r * 33 + c];
            float4 o;
            o.x = fmaxf(v.x + sBias[c * 4 + 0], 0.f);
            o.y = fmaxf(v.y + sBias[c * 4 + 1], 0.f);
            o.z = fmaxf(v.z + sBias[c * 4 + 2], 0.f);
            o.w = fmaxf(v.w + sBias[c * 4 + 3], 0.f);
            h4[(size_t)grow * 32 + c] = o;
        }
    }
}

// ---------------- segment-mean pool + head GEMM -----------------------------
__global__ void pool_head_kernel(const float* __restrict__ Wh,
                                 const float* __restrict__ bh,
                                 float* __restrict__ out) {
    __shared__ float part[4][DIM];
    __shared__ float pooled[DIM];
    int g = blockIdx.x;
    int c = threadIdx.x & 127;
    int rg = threadIdx.x >> 7;   // 0..3
    int s = g_start[g], e = g_start[g + 1];
    float sum = 0.f;
    for (int r = s + rg; r < e; r += 4) sum += g_h2[(size_t)r * DIM + c];
    part[rg][c] = sum;
    __syncthreads();
    if (rg == 0) {
        float cnt = fmaxf((float)(e - s), 1.f);
        pooled[c] = (part[0][c] + part[1][c] + part[2][c] + part[3][c]) / cnt;
    }
    __syncthreads();
    if (rg == 0 && c < NCLS) {
        float acc = bh[c];
        #pragma unroll 4
        for (int d = 0; d < DIM; d++) acc += pooled[d] * Wh[d * NCLS + c];
        out[g * NCLS + c] = acc;
    }
}

// ---------------- launch ----------------
extern "C" void kernel_launch(void* const* d_in, const int* in_sizes, int n_in,
                              void* d_out, int out_size) {
    const float* feat = (const float*)d_in[0];
    const void*  src  = d_in[1];
    const void*  dst  = d_in[2];
    const void*  gids = d_in[3];
    const float* W    = (const float*)d_in[4];
    const float* b    = (const float*)d_in[5];
    const float* Wh   = (const float*)d_in[6];
    const float* bh   = (const float*)d_in[7];
    float* out = (float*)d_out;

    cudaFuncSetAttribute(gemm_tc_kernel,
                         cudaFuncAttributeMaxDynamicSharedMemorySize, SMEM_GEMM);

    detect_kernel<<<1, 32>>>(src);
    zero_bounds_kernel<<<(NN + 255) / 256, 256>>>(gids);
    degree_kernel<<<(NE + 255) / 256, 256>>>(src, dst);
    scan_partial_kernel<<<SB, 256>>>();
    scan_spine_kernel<<<1, 256>>>();
    scan_apply_kernel<<<SB + 1, 256>>>();   // +1 block so i==NN is covered
    fill_kernel<<<(NE + 255) / 256, 256>>>(src, dst);
    gather_kernel<<<(NN * 32 + 255) / 256, 256>>>(feat);
    gemm_tc_kernel<<<NT, 256, SMEM_GEMM>>>(W, b);
    pool_head_kernel<<<NG, 512>>>(Wh, bh, out);
}